// round 13
// baseline (speedup 1.0000x reference)
#include <cuda_runtime.h>
#include <cstdint>

// Problem constants: R_MAX=32, S_MAX=2, C_Z=128, IN_FEATS=139
#define C_Z      128
#define IN_FEATS 139

// Global fused table layout (rows of 128 floats):
//   [0,66)    a rows:    Wt[dres]
//   [66,132)  b rows:    Wt[66+dtok]
//   [132,138) c rows:    ec<5 ? Wt[132]+Wt[133+ec] : Wt[138]
//   [138,144) bc rows:   b_sent + c_ec              (b_sent = Wt[131])
//   [144,150) abc rows:  a_sent + b_sent + c_ec     (a_sent = Wt[65])
//   [150,156) a32c rows: a[32] + c_ec               (ri==rj: dres==32)
#define GROW_B    66
#define GTAB_ROWS 156

// Shared-memory table (a rows as-is; fused rows at global_row - 72):
//   [0,66) a | [66,72) bc | [72,78) abc | [78,84) a32c
#define S_A     0
#define S_BC    66
#define S_ABC   72
#define S_A32C  78
#define S_ROWS  84

#define N_MAX   1024
#define NH_MAX  (N_MAX / 2)

// pk (u16): r0(7b) | r1val(7b)<<7 | TWO<<14 | GB<<15
//   case1: r1val = bc row index; case2 (GB): r1val = dtok (b row = GROW_B+dtok)
#define PK_TWO  (1u << 14)
#define PK_GB   (1u << 15)

__device__ float g_tab[GTAB_ROWS * C_Z];

// ---------------------------------------------------------------------------
// Pre-kernel: build fused table. W: [C_Z, IN_FEATS] row-major,
// Wt[f][c] = W[c*IN_FEATS + f]. Triggers PDL completion after its store.
// ---------------------------------------------------------------------------
__global__ void build_tables_kernel(const float* __restrict__ W) {
    int r = blockIdx.x;          // 0..155
    int c = threadIdx.x;         // 0..127
    const float* wc = W + (size_t)c * IN_FEATS;

    float a_sent = wc[65];
    float b_sent = wc[131];
    float a32    = wc[32];

    float v;
    if (r < 132) {
        v = wc[r];                                   // a rows, b rows
    } else {
        int k = (r - 132) % 6;                       // ec class
        float ck = (k < 5) ? (wc[132] + wc[133 + k]) : wc[138];
        if      (r < 138) v = ck;                    // c rows
        else if (r < 144) v = b_sent + ck;           // bc rows
        else if (r < 150) v = a_sent + b_sent + ck;  // abc rows
        else              v = a32 + ck;              // a32c rows
    }
    g_tab[r * C_Z + c] = v;

#if __CUDA_ARCH__ >= 900
    cudaTriggerProgrammaticLaunchCompletion();
#endif
}

// ---------------------------------------------------------------------------
// Compute one output row value from a pk (smem + rare global add).
// ---------------------------------------------------------------------------
__device__ __forceinline__ float4 row_value(unsigned pk, const float4* t4,
                                            const float4* gb4, int lane) {
    float4 v = t4[(pk & 127) * 32 + lane];
    const int r1v = (int)((pk >> 7) & 127);
    if (pk & PK_TWO) {
        const float4 b = t4[r1v * 32 + lane];
        v.x += b.x; v.y += b.y; v.z += b.z; v.w += b.w;
    }
    if (pk & PK_GB) {
        const float4 g = __ldg(gb4 + r1v * 32 + lane);
        v.x += g.x; v.y += g.y; v.z += g.z; v.w += g.w;
    }
    return v;
}

// ---------------------------------------------------------------------------
// Main kernel: TWO blocks per query row i; block handles half the j-range.
// grid = 2N = 2048, smem = 84-row table (43K) + 1K pk -> 5 CTAs/SM.
// PDL: phase 1 (pk computation, inputs only) runs BEFORE the grid dependency
// sync, hiding the build_tables kernel; table copy + phase 2 after.
// Phase 2: 8 j's per warp sweep; if all 8 pk equal (~70%), 1 LDS serves 8 STG.
// ---------------------------------------------------------------------------
__global__ __launch_bounds__(256, 5)
void relpos_kernel(const int* __restrict__ asym,
                   const int* __restrict__ resi,
                   const int* __restrict__ ent,
                   const int* __restrict__ sym,
                   const int* __restrict__ tok,
                   float* __restrict__ out,
                   int N) {
    extern __shared__ float s_mem[];
    float*          s_tab = s_mem;                                   // 84*128 floats
    unsigned short* s_pk  = (unsigned short*)(s_mem + S_ROWS * C_Z); // NH entries

    const int NH    = N >> 1;
    const int i     = blockIdx.x >> 1;
    const int jbase = (blockIdx.x & 1) * NH;

    const int ai = asym[i], ri = resi[i], ei = ent[i], si = sym[i], ti = tok[i];

    // ---- phase 1: packed indices (inputs only — overlaps build_tables) ----
    for (int jj = threadIdx.x; jj < NH; jj += blockDim.x) {
        const int j = jbase + jj;
        const int aj = __ldg(asym + j);
        const int rj = __ldg(resi + j);
        const int ej = __ldg(ent  + j);
        const int sj = __ldg(sym  + j);
        const int tj = __ldg(tok  + j);

        int ec = (ei == ej) ? min(max(si - sj + 2, 0), 4) : 5;

        unsigned pk;
        if (ai != aj) {
            pk = (unsigned)(S_ABC + ec);                       // 1 row
        } else if (ri != rj) {
            int dres = min(max(ri - rj + 32, 0), 64);
            pk = (unsigned)(S_A + dres)
               | ((unsigned)(S_BC + ec) << 7) | PK_TWO;        // 2 rows
        } else {
            // dres == 32 exactly; a[32] folded into a32c[ec]; b row global.
            int dtok = min(max(ti - tj + 32, 0), 64);
            pk = (unsigned)(S_A32C + ec)
               | ((unsigned)dtok << 7) | PK_GB;                // 1 row + global
        }
        s_pk[jj] = (unsigned short)pk;
    }

    // ---- wait for build_tables, then copy the 84-row table ----
#if __CUDA_ARCH__ >= 900
    cudaGridDependencySynchronize();
#endif
    {
        const float4* src = (const float4*)g_tab;
        float4*       dst = (float4*)s_tab;
        for (int k = threadIdx.x; k < S_ROWS * 32; k += blockDim.x) {
            int s_row = k >> 5;
            int g_row = (s_row < 66) ? s_row : s_row + 72;
            dst[k] = src[g_row * 32 + (k & 31)];
        }
    }
    __syncthreads();

    // ---- phase 2: 8 contiguous j's per warp sweep ----
    const int lane = threadIdx.x & 31;
    const int wid  = threadIdx.x >> 5;
    const float4* t4  = (const float4*)s_tab;                  // [84][32]
    const float4* gb4 = (const float4*)(g_tab + GROW_B * C_Z);
    float* out_b = out + ((size_t)i * N + jbase) * C_Z;

    for (int jj0 = wid * 8; jj0 < NH; jj0 += 64) {
        const uint4 q = *(const uint4*)(s_pk + jj0);           // 8 pk via LDS.128
        float4* dst = (float4*)(out_b + (size_t)jj0 * C_Z) + lane;

        const bool uni = (q.x == q.y) & (q.x == q.z) & (q.x == q.w)
                       & ((q.x >> 16) == (q.x & 0xffffu));
        if (uni) {
            // fast path (~70% of sweeps): one row serves 8 stores
            const float4 v = row_value(q.x & 0xffffu, t4, gb4, lane);
            #pragma unroll
            for (int u = 0; u < 8; u++)
                __stcs(dst + u * 32, v);
        } else {
            const unsigned pks[8] = {
                q.x & 0xffffu, q.x >> 16, q.y & 0xffffu, q.y >> 16,
                q.z & 0xffffu, q.z >> 16, q.w & 0xffffu, q.w >> 16
            };
            #pragma unroll
            for (int g = 0; g < 2; g++) {
                float4 v[4];
                #pragma unroll
                for (int u = 0; u < 4; u++)
                    v[u] = row_value(pks[g * 4 + u], t4, gb4, lane);
                #pragma unroll
                for (int u = 0; u < 4; u++)
                    __stcs(dst + (g * 4 + u) * 32, v[u]);
            }
        }
    }
}

extern "C" void kernel_launch(void* const* d_in, const int* in_sizes, int n_in,
                              void* d_out, int out_size) {
    const float* W    = (const float*)d_in[0];
    const int*   asym = (const int*)d_in[1];
    const int*   resi = (const int*)d_in[2];
    const int*   ent  = (const int*)d_in[3];
    const int*   sym  = (const int*)d_in[4];
    const int*   tok  = (const int*)d_in[5];
    float*       out  = (float*)d_out;

    const int N = in_sizes[1];   // 1024

    const int smem = S_ROWS * C_Z * (int)sizeof(float)
                   + NH_MAX * (int)sizeof(unsigned short);     // 44032 B
    cudaFuncSetAttribute(relpos_kernel,
                         cudaFuncAttributeMaxDynamicSharedMemorySize, smem);

    build_tables_kernel<<<GTAB_ROWS, C_Z>>>(W);

    // PDL launch: overlap relpos phase 1 with build_tables.
    cudaLaunchConfig_t cfg = {};
    cfg.gridDim          = dim3(2 * N, 1, 1);
    cfg.blockDim         = dim3(256, 1, 1);
    cfg.dynamicSmemBytes = (size_t)smem;
    cfg.stream           = 0;
    cudaLaunchAttribute attrs[1];
    attrs[0].id = cudaLaunchAttributeProgrammaticStreamSerialization;
    attrs[0].val.programmaticStreamSerializationAllowed = 1;
    cfg.attrs    = attrs;
    cfg.numAttrs = 1;
    cudaLaunchKernelEx(&cfg, relpos_kernel, asym, resi, ent, sym, tok, out, N);
}

// round 14
// speedup vs baseline: 1.0062x; 1.0062x over previous
#include <cuda_runtime.h>
#include <cstdint>

// Problem constants: R_MAX=32, S_MAX=2, C_Z=128, IN_FEATS=139
#define C_Z      128
#define IN_FEATS 139

// Global fused table layout (rows of 128 floats):
//   [0,66)    a rows:    Wt[dres]
//   [66,132)  b rows:    Wt[66+dtok]
//   [132,138) c rows:    ec<5 ? Wt[132]+Wt[133+ec] : Wt[138]
//   [138,144) bc rows:   b_sent + c_ec              (b_sent = Wt[131])
//   [144,150) abc rows:  a_sent + b_sent + c_ec     (a_sent = Wt[65])
//   [150,156) a32c rows: a[32] + c_ec               (ri==rj: dres==32)
#define GROW_B    66
#define GTAB_ROWS 156

// Shared-memory table (a rows as-is; fused rows at global_row - 72):
//   [0,66) a | [66,72) bc | [72,78) abc | [78,84) a32c
#define S_A     0
#define S_BC    66
#define S_ABC   72
#define S_A32C  78
#define S_ROWS  84

#define N_MAX   1024
#define NH_MAX  (N_MAX / 2)

// pk (u16): r0(7b) | r1val(7b)<<7 | TWO<<14 | GB<<15
//   case1: r1val = bc row index; case2 (GB): r1val = dtok (b row = GROW_B+dtok)
#define PK_TWO  (1u << 14)
#define PK_GB   (1u << 15)

__device__ float g_tab[GTAB_ROWS * C_Z];

// ---------------------------------------------------------------------------
// Pre-kernel: build fused table. W: [C_Z, IN_FEATS] row-major,
// Wt[f][c] = W[c*IN_FEATS + f]. Triggers PDL completion after its store.
// ---------------------------------------------------------------------------
__global__ void build_tables_kernel(const float* __restrict__ W) {
    int r = blockIdx.x;          // 0..155
    int c = threadIdx.x;         // 0..127
    const float* wc = W + (size_t)c * IN_FEATS;

    float a_sent = wc[65];
    float b_sent = wc[131];
    float a32    = wc[32];

    float v;
    if (r < 132) {
        v = wc[r];                                   // a rows, b rows
    } else {
        int k = (r - 132) % 6;                       // ec class
        float ck = (k < 5) ? (wc[132] + wc[133 + k]) : wc[138];
        if      (r < 138) v = ck;                    // c rows
        else if (r < 144) v = b_sent + ck;           // bc rows
        else if (r < 150) v = a_sent + b_sent + ck;  // abc rows
        else              v = a32 + ck;              // a32c rows
    }
    g_tab[r * C_Z + c] = v;

#if __CUDA_ARCH__ >= 900
    cudaTriggerProgrammaticLaunchCompletion();
#endif
}

// ---------------------------------------------------------------------------
// Compute one output row value from a pk (smem + rare global add).
// ---------------------------------------------------------------------------
__device__ __forceinline__ float4 row_value(unsigned pk, const float4* t4,
                                            const float4* gb4, int lane) {
    float4 v = t4[(pk & 127) * 32 + lane];
    const int r1v = (int)((pk >> 7) & 127);
    if (pk & PK_TWO) {
        const float4 b = t4[r1v * 32 + lane];
        v.x += b.x; v.y += b.y; v.z += b.z; v.w += b.w;
    }
    if (pk & PK_GB) {
        const float4 g = __ldg(gb4 + r1v * 32 + lane);
        v.x += g.x; v.y += g.y; v.z += g.z; v.w += g.w;
    }
    return v;
}

// ---------------------------------------------------------------------------
// Main kernel: TWO blocks per query row i; block handles half the j-range.
// grid = 2N = 2048, smem = 84-row table (43K) + 1K pk -> 5 CTAs/SM.
// PDL: phase 1 (pk computation, inputs only) runs BEFORE the grid dependency
// sync, hiding build_tables; table copy + phase 2 after.
// Phase 2 (R12-proven): 4 j's per warp sweep; if all 4 pk equal (~75%),
// one LDS.128 serves 4 STG.128.
// ---------------------------------------------------------------------------
__global__ __launch_bounds__(256, 5)
void relpos_kernel(const int* __restrict__ asym,
                   const int* __restrict__ resi,
                   const int* __restrict__ ent,
                   const int* __restrict__ sym,
                   const int* __restrict__ tok,
                   float* __restrict__ out,
                   int N) {
    extern __shared__ float s_mem[];
    float*          s_tab = s_mem;                                   // 84*128 floats
    unsigned short* s_pk  = (unsigned short*)(s_mem + S_ROWS * C_Z); // NH entries

    const int NH    = N >> 1;
    const int i     = blockIdx.x >> 1;
    const int jbase = (blockIdx.x & 1) * NH;

    const int ai = asym[i], ri = resi[i], ei = ent[i], si = sym[i], ti = tok[i];

    // ---- phase 1: packed indices (inputs only — overlaps build_tables) ----
    for (int jj = threadIdx.x; jj < NH; jj += blockDim.x) {
        const int j = jbase + jj;
        const int aj = __ldg(asym + j);
        const int rj = __ldg(resi + j);
        const int ej = __ldg(ent  + j);
        const int sj = __ldg(sym  + j);
        const int tj = __ldg(tok  + j);

        int ec = (ei == ej) ? min(max(si - sj + 2, 0), 4) : 5;

        unsigned pk;
        if (ai != aj) {
            pk = (unsigned)(S_ABC + ec);                       // 1 row
        } else if (ri != rj) {
            int dres = min(max(ri - rj + 32, 0), 64);
            pk = (unsigned)(S_A + dres)
               | ((unsigned)(S_BC + ec) << 7) | PK_TWO;        // 2 rows
        } else {
            // dres == 32 exactly; a[32] folded into a32c[ec]; b row global.
            int dtok = min(max(ti - tj + 32, 0), 64);
            pk = (unsigned)(S_A32C + ec)
               | ((unsigned)dtok << 7) | PK_GB;                // 1 row + global
        }
        s_pk[jj] = (unsigned short)pk;
    }

    // ---- wait for build_tables, then copy the 84-row table ----
#if __CUDA_ARCH__ >= 900
    cudaGridDependencySynchronize();
#endif
    {
        const float4* src = (const float4*)g_tab;
        float4*       dst = (float4*)s_tab;
        for (int k = threadIdx.x; k < S_ROWS * 32; k += blockDim.x) {
            int s_row = k >> 5;
            int g_row = (s_row < 66) ? s_row : s_row + 72;
            dst[k] = src[g_row * 32 + (k & 31)];
        }
    }
    __syncthreads();

    // ---- phase 2: 4 contiguous j's per warp sweep; run-uniform fast path ----
    const int lane = threadIdx.x & 31;
    const int wid  = threadIdx.x >> 5;
    const float4* t4  = (const float4*)s_tab;                  // [84][32]
    const float4* gb4 = (const float4*)(g_tab + GROW_B * C_Z);
    float* out_b = out + ((size_t)i * N + jbase) * C_Z;

    for (int jj0 = wid * 4; jj0 < NH; jj0 += 32) {
        const ushort4 pkv = *(const ushort4*)(s_pk + jj0);     // broadcast LDS.64
        float4* dst = (float4*)(out_b + (size_t)jj0 * C_Z) + lane;

        if ((pkv.x == pkv.y) & (pkv.y == pkv.z) & (pkv.z == pkv.w)) {
            // fast path (~75% of sweeps): one load serves 4 stores
            const float4 v = row_value(pkv.x, t4, gb4, lane);
            __stcs(dst,      v);
            __stcs(dst + 32, v);
            __stcs(dst + 64, v);
            __stcs(dst + 96, v);
        } else {
            unsigned pks[4] = {pkv.x, pkv.y, pkv.z, pkv.w};
            float4 v[4];
            #pragma unroll
            for (int u = 0; u < 4; u++)
                v[u] = row_value(pks[u], t4, gb4, lane);
            #pragma unroll
            for (int u = 0; u < 4; u++)
                __stcs(dst + u * 32, v[u]);
        }
    }
}

extern "C" void kernel_launch(void* const* d_in, const int* in_sizes, int n_in,
                              void* d_out, int out_size) {
    const float* W    = (const float*)d_in[0];
    const int*   asym = (const int*)d_in[1];
    const int*   resi = (const int*)d_in[2];
    const int*   ent  = (const int*)d_in[3];
    const int*   sym  = (const int*)d_in[4];
    const int*   tok  = (const int*)d_in[5];
    float*       out  = (float*)d_out;

    const int N = in_sizes[1];   // 1024

    const int smem = S_ROWS * C_Z * (int)sizeof(float)
                   + NH_MAX * (int)sizeof(unsigned short);     // 44032 B
    cudaFuncSetAttribute(relpos_kernel,
                         cudaFuncAttributeMaxDynamicSharedMemorySize, smem);

    build_tables_kernel<<<GTAB_ROWS, C_Z>>>(W);

    // PDL launch: overlap relpos phase 1 with build_tables.
    cudaLaunchConfig_t cfg = {};
    cfg.gridDim          = dim3(2 * N, 1, 1);
    cfg.blockDim         = dim3(256, 1, 1);
    cfg.dynamicSmemBytes = (size_t)smem;
    cfg.stream           = 0;
    cudaLaunchAttribute attrs[1];
    attrs[0].id = cudaLaunchAttributeProgrammaticStreamSerialization;
    attrs[0].val.programmaticStreamSerializationAllowed = 1;
    cfg.attrs    = attrs;
    cfg.numAttrs = 1;
    cudaLaunchKernelEx(&cfg, relpos_kernel, asym, resi, ent, sym, tok, out, N);
}

// round 15
// speedup vs baseline: 1.0091x; 1.0029x over previous
#include <cuda_runtime.h>
#include <cstdint>

// Problem constants: R_MAX=32, S_MAX=2, C_Z=128, IN_FEATS=139
#define C_Z      128
#define IN_FEATS 139

// Global fused table layout (rows of 128 floats):
//   [0,66)    a rows:    Wt[dres]
//   [66,132)  b rows:    Wt[66+dtok]
//   [132,138) c rows:    ec<5 ? Wt[132]+Wt[133+ec] : Wt[138]
//   [138,144) bc rows:   b_sent + c_ec              (b_sent = Wt[131])
//   [144,150) abc rows:  a_sent + b_sent + c_ec     (a_sent = Wt[65])
//   [150,156) a32c rows: a[32] + c_ec               (ri==rj: dres==32)
#define GROW_B    66
#define GTAB_ROWS 156

// Shared-memory table (a rows as-is; fused rows at global_row - 72):
//   [0,66) a | [66,72) bc | [72,78) abc | [78,84) a32c
#define S_A     0
#define S_BC    66
#define S_ABC   72
#define S_A32C  78
#define S_ROWS  84

#define N_MAX   1024
#define NH_MAX  (N_MAX / 2)

// pk (u16): r0(7b) | r1val(7b)<<7 | TWO<<14 | GB<<15
//   case1: r1val = bc row index; case2 (GB): r1val = dtok (b row = GROW_B+dtok)
#define PK_TWO  (1u << 14)
#define PK_GB   (1u << 15)

__device__ float g_tab[GTAB_ROWS * C_Z];

// ---------------------------------------------------------------------------
// Pre-kernel: build fused table. W: [C_Z, IN_FEATS] row-major,
// Wt[f][c] = W[c*IN_FEATS + f]. Triggers PDL completion after its store.
// ---------------------------------------------------------------------------
__global__ void build_tables_kernel(const float* __restrict__ W) {
    int r = blockIdx.x;          // 0..155
    int c = threadIdx.x;         // 0..127
    const float* wc = W + (size_t)c * IN_FEATS;

    float a_sent = wc[65];
    float b_sent = wc[131];
    float a32    = wc[32];

    float v;
    if (r < 132) {
        v = wc[r];                                   // a rows, b rows
    } else {
        int k = (r - 132) % 6;                       // ec class
        float ck = (k < 5) ? (wc[132] + wc[133 + k]) : wc[138];
        if      (r < 138) v = ck;                    // c rows
        else if (r < 144) v = b_sent + ck;           // bc rows
        else if (r < 150) v = a_sent + b_sent + ck;  // abc rows
        else              v = a32 + ck;              // a32c rows
    }
    g_tab[r * C_Z + c] = v;

#if __CUDA_ARCH__ >= 900
    cudaTriggerProgrammaticLaunchCompletion();
#endif
}

// ---------------------------------------------------------------------------
// Compute one output row value from a pk (smem + rare global add).
// ---------------------------------------------------------------------------
__device__ __forceinline__ float4 row_value(unsigned pk, const float4* t4,
                                            const float4* gb4, int lane) {
    float4 v = t4[(pk & 127) * 32 + lane];
    const int r1v = (int)((pk >> 7) & 127);
    if (pk & PK_TWO) {
        const float4 b = t4[r1v * 32 + lane];
        v.x += b.x; v.y += b.y; v.z += b.z; v.w += b.w;
    }
    if (pk & PK_GB) {
        const float4 g = __ldg(gb4 + r1v * 32 + lane);
        v.x += g.x; v.y += g.y; v.z += g.z; v.w += g.w;
    }
    return v;
}

// ---------------------------------------------------------------------------
// Main kernel: TWO blocks per query row i; block handles half the j-range.
// grid = 2N = 2048, smem = 84-row table (43K) + 1K pk -> 5 CTAs/SM.
// PDL: gridsync at the VERY TOP (overlaps launch/prologue with build_tables),
// then the body is the proven R12 structure: table copy -> phase 1 -> sync ->
// 4-wide run-uniform phase 2 (copy and phase-1 loads freely interleave).
// ---------------------------------------------------------------------------
__global__ __launch_bounds__(256, 5)
void relpos_kernel(const int* __restrict__ asym,
                   const int* __restrict__ resi,
                   const int* __restrict__ ent,
                   const int* __restrict__ sym,
                   const int* __restrict__ tok,
                   float* __restrict__ out,
                   int N) {
#if __CUDA_ARCH__ >= 900
    cudaGridDependencySynchronize();
#endif

    extern __shared__ float s_mem[];
    float*          s_tab = s_mem;                                   // 84*128 floats
    unsigned short* s_pk  = (unsigned short*)(s_mem + S_ROWS * C_Z); // NH entries

    // ---- table copy: 84 rows (a rows as-is, fused rows at g_row = s+72) ----
    {
        const float4* src = (const float4*)g_tab;
        float4*       dst = (float4*)s_tab;
        for (int k = threadIdx.x; k < S_ROWS * 32; k += blockDim.x) {
            int s_row = k >> 5;
            int g_row = (s_row < 66) ? s_row : s_row + 72;
            dst[k] = src[g_row * 32 + (k & 31)];
        }
    }

    const int NH    = N >> 1;
    const int i     = blockIdx.x >> 1;
    const int jbase = (blockIdx.x & 1) * NH;

    const int ai = asym[i], ri = resi[i], ei = ent[i], si = sym[i], ti = tok[i];

    // ---- phase 1: packed indices for this block's half of j ----
    for (int jj = threadIdx.x; jj < NH; jj += blockDim.x) {
        const int j = jbase + jj;
        const int aj = __ldg(asym + j);
        const int rj = __ldg(resi + j);
        const int ej = __ldg(ent  + j);
        const int sj = __ldg(sym  + j);
        const int tj = __ldg(tok  + j);

        int ec = (ei == ej) ? min(max(si - sj + 2, 0), 4) : 5;

        unsigned pk;
        if (ai != aj) {
            pk = (unsigned)(S_ABC + ec);                       // 1 row
        } else if (ri != rj) {
            int dres = min(max(ri - rj + 32, 0), 64);
            pk = (unsigned)(S_A + dres)
               | ((unsigned)(S_BC + ec) << 7) | PK_TWO;        // 2 rows
        } else {
            // dres == 32 exactly; a[32] folded into a32c[ec]; b row global.
            int dtok = min(max(ti - tj + 32, 0), 64);
            pk = (unsigned)(S_A32C + ec)
               | ((unsigned)dtok << 7) | PK_GB;                // 1 row + global
        }
        s_pk[jj] = (unsigned short)pk;
    }
    __syncthreads();

    // ---- phase 2: 4 contiguous j's per warp sweep; run-uniform fast path ----
    const int lane = threadIdx.x & 31;
    const int wid  = threadIdx.x >> 5;
    const float4* t4  = (const float4*)s_tab;                  // [84][32]
    const float4* gb4 = (const float4*)(g_tab + GROW_B * C_Z);
    float* out_b = out + ((size_t)i * N + jbase) * C_Z;

    for (int jj0 = wid * 4; jj0 < NH; jj0 += 32) {
        const ushort4 pkv = *(const ushort4*)(s_pk + jj0);     // broadcast LDS.64
        float4* dst = (float4*)(out_b + (size_t)jj0 * C_Z) + lane;

        if ((pkv.x == pkv.y) & (pkv.y == pkv.z) & (pkv.z == pkv.w)) {
            // fast path (~75% of sweeps): one load serves 4 stores
            const float4 v = row_value(pkv.x, t4, gb4, lane);
            __stcs(dst,      v);
            __stcs(dst + 32, v);
            __stcs(dst + 64, v);
            __stcs(dst + 96, v);
        } else {
            unsigned pks[4] = {pkv.x, pkv.y, pkv.z, pkv.w};
            float4 v[4];
            #pragma unroll
            for (int u = 0; u < 4; u++)
                v[u] = row_value(pks[u], t4, gb4, lane);
            #pragma unroll
            for (int u = 0; u < 4; u++)
                __stcs(dst + u * 32, v[u]);
        }
    }
}

extern "C" void kernel_launch(void* const* d_in, const int* in_sizes, int n_in,
                              void* d_out, int out_size) {
    const float* W    = (const float*)d_in[0];
    const int*   asym = (const int*)d_in[1];
    const int*   resi = (const int*)d_in[2];
    const int*   ent  = (const int*)d_in[3];
    const int*   sym  = (const int*)d_in[4];
    const int*   tok  = (const int*)d_in[5];
    float*       out  = (float*)d_out;

    const int N = in_sizes[1];   // 1024

    const int smem = S_ROWS * C_Z * (int)sizeof(float)
                   + NH_MAX * (int)sizeof(unsigned short);     // 44032 B
    cudaFuncSetAttribute(relpos_kernel,
                         cudaFuncAttributeMaxDynamicSharedMemorySize, smem);

    build_tables_kernel<<<GTAB_ROWS, C_Z>>>(W);

    // PDL launch: overlap relpos launch/prologue with build_tables.
    cudaLaunchConfig_t cfg = {};
    cfg.gridDim          = dim3(2 * N, 1, 1);
    cfg.blockDim         = dim3(256, 1, 1);
    cfg.dynamicSmemBytes = (size_t)smem;
    cfg.stream           = 0;
    cudaLaunchAttribute attrs[1];
    attrs[0].id = cudaLaunchAttributeProgrammaticStreamSerialization;
    attrs[0].val.programmaticStreamSerializationAllowed = 1;
    cfg.attrs    = attrs;
    cfg.numAttrs = 1;
    cudaLaunchKernelEx(&cfg, relpos_kernel, asym, resi, ent, sym, tok, out, N);
}